// round 9
// baseline (speedup 1.0000x reference)
#include <cuda_runtime.h>
#include <cstdint>

// Problem: states [B=64, L=4096, D=256] f32; w [256] f32; bias scalar f32.
// out[b,l] = reverse_cumsum_l( dot(states[b,l,:], w) + bias )
//
// Single fused kernel, TWO blocks per batch (128 blocks <= 148 SMs, all
// co-resident in wave 1 => spin-wait is deadlock-free):
//   block (b, h) owns rows [h*2048, h*2048+2048) of batch b.
//   Phase 1: 32 warps x 64 rows, warp-per-row dot (__ldcs stream loads),
//            values parked in smem.
//   Phase 2: block-local suffix scan of its 2048 values.
//   Cross-block: h=1 publishes its half-total as one 64-bit (flag,total)
//   word; h=0 spins on it (once, at the end), adds it to its outputs.
// 128 streaming SMs => per-SM demand ~51 GB/s, well under the ~92 GB/s/SM
// ceiling measured in R7, so HBM should return to ~87% as in R5.

static constexpr int B = 64;
static constexpr int L = 4096;
static constexpr int HALF = L / 2;        // 2048
static constexpr int D = 256;             // 64 float4 per row
static constexpr int T = 1024;
static constexpr int WARPS = T / 32;      // 32
static constexpr int ROWS_PER_WARP = HALF / WARPS;  // 64

// (flag<<32 | float_bits(total)) per batch; reset to 0 by the consumer so
// every graph replay starts clean. Zero-initialized at module load.
__device__ unsigned long long g_sync[B];

__global__ void __launch_bounds__(1024, 1)
qvalue_kernel(const float4* __restrict__ states4,
              const float4* __restrict__ w4,
              const float*  __restrict__ bias,
              float* __restrict__ out)
{
    __shared__ float vals[HALF];          // 8 KB
    __shared__ float warp_tot[WARPS];
    __shared__ float warp_off[WARPS];
    __shared__ float other_half_total;

    const int b    = blockIdx.x >> 1;
    const int h    = blockIdx.x & 1;      // 0 = front half, 1 = back half
    const int t    = threadIdx.x;
    const int lane = t & 31;
    const int wid  = t >> 5;

    const float4 w0 = __ldg(&w4[lane]);
    const float4 w1 = __ldg(&w4[lane + 32]);
    const float  bv = __ldg(bias);

    // this block's slab: rows [h*HALF, h*HALF+HALF) of batch b
    const float4* slab = states4
        + ((size_t)b * L + (size_t)h * HALF) * (D / 4);

    // ---- phase 1: warp-per-row dot products ----
    #pragma unroll 4
    for (int i = 0; i < ROWS_PER_WARP; i += 2) {
        const int l0 = wid + (i    ) * WARPS;
        const int l1 = wid + (i + 1) * WARPS;
        const float4* r0 = slab + (size_t)l0 * (D / 4);
        const float4* r1 = slab + (size_t)l1 * (D / 4);

        float4 a0 = __ldcs(&r0[lane]);
        float4 a1 = __ldcs(&r0[lane + 32]);
        float4 c0 = __ldcs(&r1[lane]);
        float4 c1 = __ldcs(&r1[lane + 32]);

        float s0 = a0.x * w0.x + a0.y * w0.y + a0.z * w0.z + a0.w * w0.w
                 + a1.x * w1.x + a1.y * w1.y + a1.z * w1.z + a1.w * w1.w;
        float s1 = c0.x * w0.x + c0.y * w0.y + c0.z * w0.z + c0.w * w0.w
                 + c1.x * w1.x + c1.y * w1.y + c1.z * w1.z + c1.w * w1.w;

        #pragma unroll
        for (int off = 16; off > 0; off >>= 1) {
            s0 += __shfl_xor_sync(0xFFFFFFFFu, s0, off);
            s1 += __shfl_xor_sync(0xFFFFFFFFu, s1, off);
        }

        if (lane == 0) {
            vals[l0] = s0 + bv;
            vals[l1] = s1 + bv;
        }
    }
    __syncthreads();

    // ---- phase 2: block-local suffix scan over vals[0..HALF) ----
    // thread t owns 2 contiguous elements [2t, 2t+2)
    float v0 = vals[2 * t + 0];
    float v1 = vals[2 * t + 1];
    float total = v0 + v1;

    // inclusive SUFFIX scan within warp: lane i -> sum over lanes >= i
    float s = total;
    #pragma unroll
    for (int off = 1; off < 32; off <<= 1) {
        float n = __shfl_down_sync(0xFFFFFFFFu, s, off);
        if (lane < 32 - off) s += n;
    }

    if (lane == 0) warp_tot[wid] = s;     // warp's full sum
    __syncthreads();

    if (wid == 0) {
        float ws = warp_tot[lane];
        float ss = ws;
        #pragma unroll
        for (int off = 1; off < 32; off <<= 1) {
            float n = __shfl_down_sync(0xFFFFFFFFu, ss, off);
            if (lane < 32 - off) ss += n;
        }
        warp_off[lane] = ss - ws;         // exclusive suffix of warp sums
        if (lane == 0 && h == 1) {
            // publish this (back) half's grand total: ss at lane 0
            unsigned long long pkt =
                (1ULL << 32) | (unsigned long long)__float_as_uint(ss);
            *((volatile unsigned long long*)&g_sync[b]) = pkt;
        }
    }
    __syncthreads();

    float offset = warp_off[wid] + (s - total);   // suffix strictly after me

    // front half must add the back half's grand total
    if (h == 0) {
        if (t == 0) {
            volatile unsigned long long* sp =
                (volatile unsigned long long*)&g_sync[b];
            unsigned long long x;
            do { x = *sp; } while ((x >> 32) == 0ULL);
            other_half_total = __uint_as_float((unsigned)(x & 0xFFFFFFFFULL));
            *sp = 0ULL;                   // reset for next graph replay
        }
        __syncthreads();
        offset += other_half_total;
    }

    float q1 = offset + v1;
    float q0 = q1 + v0;

    reinterpret_cast<float2*>(out + (size_t)b * L + (size_t)h * HALF)[t] =
        make_float2(q0, q1);
}

extern "C" void kernel_launch(void* const* d_in, const int* in_sizes, int n_in,
                              void* d_out, int out_size)
{
    const float4* states4 = (const float4*)d_in[0];
    const float4* w4      = (const float4*)d_in[1];
    const float*  bias    = (const float*)d_in[2];
    float* out = (float*)d_out;

    qvalue_kernel<<<2 * B, T>>>(states4, w4, bias, out);
}

// round 10
// speedup vs baseline: 1.0077x; 1.0077x over previous
#include <cuda_runtime.h>
#include <cstdint>

// Problem: states [B=64, L=4096, D=256] f32; w [256] f32; bias scalar f32.
// out[b,l] = reverse_cumsum_l( dot(states[b,l,:], w) + bias )
//
// Kernel 1 (proven 87%-of-HBM shape): 256-thr blocks, 1 warp per row,
//   __ldcs stream loads. NEW: each block also stores the sum of its 8
//   values into partials[bid] (plain STG — no atomics/fences; kernel
//   boundary provides visibility; overwrite => replay-safe).
// Kernel 2: 1024 INDEPENDENT blocks (64 batches x 16 chunks of 256 l).
//   Each block computes its chunk offset from the batch's 512 partials
//   (suffix beyond its chunk), block-scans its 256 values, writes out.
//   No cross-block dependency -> latency fully overlapped.

static constexpr int B = 64;
static constexpr int L = 4096;
static constexpr int D = 256;                  // 64 float4 per row
static constexpr int ROWS = B * L;             // 262144
static constexpr int BLOCKS1 = ROWS / 8;       // 32768 dot blocks
static constexpr int PART_PER_B = 512;         // 4096 / 8
static constexpr int CHUNK = 256;              // l's per kernel-2 block
static constexpr int CHUNKS_PER_B = L / CHUNK; // 16
static constexpr int PART_PER_CHUNK = CHUNK / 8; // 32

__device__ float g_partials[BLOCKS1];          // 128 KB scratch, overwritten

__global__ void __launch_bounds__(256)
dot_kernel(const float4* __restrict__ states4,
           const float4* __restrict__ w4,
           const float*  __restrict__ bias,
           float* __restrict__ out)
{
    __shared__ float wsum[8];

    int gwarp = (blockIdx.x << 3) + (threadIdx.x >> 5);
    int lane  = threadIdx.x & 31;
    int wid   = threadIdx.x >> 5;

    const float4* row = states4 + (size_t)gwarp * (D / 4);

    // streaming loads, evict-first: states touched exactly once
    float4 a0 = __ldcs(&row[lane]);
    float4 a1 = __ldcs(&row[lane + 32]);
    float4 w0 = __ldg(&w4[lane]);
    float4 w1 = __ldg(&w4[lane + 32]);

    float s = a0.x * w0.x + a0.y * w0.y + a0.z * w0.z + a0.w * w0.w
            + a1.x * w1.x + a1.y * w1.y + a1.z * w1.z + a1.w * w1.w;

    #pragma unroll
    for (int off = 16; off > 0; off >>= 1)
        s += __shfl_xor_sync(0xFFFFFFFFu, s, off);

    float val = s + __ldg(bias);
    if (lane == 0) {
        out[gwarp] = val;
        wsum[wid] = val;
    }
    __syncthreads();

    // block partial sum (8 warp values) -> partials[bid]
    if (wid == 0) {
        float p = (lane < 8) ? wsum[lane] : 0.f;
        #pragma unroll
        for (int off = 4; off > 0; off >>= 1)
            p += __shfl_xor_sync(0xFFFFFFFFu, p, off);
        if (lane == 0)
            g_partials[blockIdx.x] = p;
    }
}

// 1024 independent blocks: block (b, c) finalizes out[b, c*256 .. c*256+256)
__global__ void __launch_bounds__(256)
rcumsum_kernel(float* __restrict__ out)
{
    __shared__ float red[8];
    __shared__ float warp_tot[8];
    __shared__ float warp_off[8];
    __shared__ float chunk_off_sh;

    const int b    = blockIdx.x >> 4;          // / CHUNKS_PER_B
    const int c    = blockIdx.x & 15;
    const int t    = threadIdx.x;
    const int lane = t & 31;
    const int wid  = t >> 5;

    // ---- chunk offset: sum of partials strictly AFTER this chunk ----
    const float* bp = g_partials + b * PART_PER_B;
    const int first_excl = (c + 1) * PART_PER_CHUNK;   // 32*(c+1)

    float part = 0.f;
    {
        int j0 = t, j1 = t + 256;
        float p0 = bp[j0];                      // always in-range (512)
        float p1 = bp[j1 & 511];
        if (j0 >= first_excl) part += p0;
        if (j1 < PART_PER_B && j1 >= first_excl) part += p1;
    }
    #pragma unroll
    for (int off = 16; off > 0; off >>= 1)
        part += __shfl_xor_sync(0xFFFFFFFFu, part, off);
    if (lane == 0) red[wid] = part;
    __syncthreads();
    if (t == 0) {
        float co = 0.f;
        #pragma unroll
        for (int w = 0; w < 8; w++) co += red[w];
        chunk_off_sh = co;
    }

    // ---- block suffix scan of 256 values, 1 per thread ----
    const int idx = b * L + c * CHUNK + t;
    float v = out[idx];

    // inclusive SUFFIX scan within warp: lane i -> sum over lanes >= i
    float s = v;
    #pragma unroll
    for (int off = 1; off < 32; off <<= 1) {
        float n = __shfl_down_sync(0xFFFFFFFFu, s, off);
        if (lane < 32 - off) s += n;
    }

    float wfull = __shfl_sync(0xFFFFFFFFu, s, 0);   // warp's full sum
    if (lane == 0) warp_tot[wid] = wfull;
    __syncthreads();

    if (wid == 0 && lane < 8) {
        float ws = warp_tot[lane];
        float ss = ws;
        #pragma unroll
        for (int off = 1; off < 8; off <<= 1) {
            float n = __shfl_down_sync(0x000000FFu, ss, off);
            if (lane < 8 - off) ss += n;
        }
        warp_off[lane] = ss - ws;        // suffix of warp sums strictly after
    }
    __syncthreads();

    // q[idx] = (chunk offset) + (warps after mine) + (suffix incl. me)
    out[idx] = chunk_off_sh + warp_off[wid] + s;
}

extern "C" void kernel_launch(void* const* d_in, const int* in_sizes, int n_in,
                              void* d_out, int out_size)
{
    const float4* states4 = (const float4*)d_in[0];
    const float4* w4      = (const float4*)d_in[1];
    const float*  bias    = (const float*)d_in[2];
    float* out = (float*)d_out;

    dot_kernel<<<BLOCKS1, 256>>>(states4, w4, bias, out);
    rcumsum_kernel<<<B * CHUNKS_PER_B, 256>>>(out);
}

// round 12
// speedup vs baseline: 1.0490x; 1.0409x over previous
#include <cuda_runtime.h>
#include <cstdint>

// Problem: states [B=64, L=4096, D=256] f32; w [256] f32; bias scalar f32.
// out[b,l] = reverse_cumsum_l( dot(states[b,l,:], w) + bias )
//
// Two kernels, linked by FULL PDL this time:
//  1) dot_kernel: exact R5 proven shape (256 thr, warp-per-row, __ldcs,
//     occ 92%, ~38.6us = 87% of HBM). Each block calls
//     cudaTriggerProgrammaticLaunchCompletion() AFTER its store, making its
//     stores visible to the dependent grid per the PDL contract.
//  2) rcumsum_kernel (64 x 1024): launched with programmaticStreamSerialization;
//     its ~4us node ramp overlaps the primary; blocks sleep in
//     cudaGridDependencySynchronize() until all primary blocks triggered.
//     Post-sync execution ~1.3us is the only exposed cost.

static constexpr int B = 64;
static constexpr int L = 4096;
static constexpr int D = 256;          // 64 float4 per row
static constexpr int ROWS = B * L;     // 262144

__global__ void __launch_bounds__(256)
dot_kernel(const float4* __restrict__ states4,
           const float4* __restrict__ w4,
           const float*  __restrict__ bias,
           float* __restrict__ out)
{
    int gwarp = (blockIdx.x * blockDim.x + threadIdx.x) >> 5;
    int lane  = threadIdx.x & 31;

    const float4* row = states4 + (size_t)gwarp * (D / 4);

    // streaming loads, evict-first: states are touched exactly once
    float4 a0 = __ldcs(&row[lane]);
    float4 a1 = __ldcs(&row[lane + 32]);
    float4 w0 = __ldg(&w4[lane]);
    float4 w1 = __ldg(&w4[lane + 32]);

    float s = a0.x * w0.x + a0.y * w0.y + a0.z * w0.z + a0.w * w0.w
            + a1.x * w1.x + a1.y * w1.y + a1.z * w1.z + a1.w * w1.w;

    #pragma unroll
    for (int off = 16; off > 0; off >>= 1)
        s += __shfl_xor_sync(0xFFFFFFFFu, s, off);

    if (lane == 0)
        out[gwarp] = s + __ldg(bias);

    // PDL: stores above become visible to the dependent grid; allows the
    // secondary to proceed once ALL primary blocks have triggered/exited.
    cudaTriggerProgrammaticLaunchCompletion();
}

// In-place reverse cumulative sum along L for each batch row.
// grid = B blocks x 1024 threads, one float4 per thread. Runs its preamble
// during the primary, sleeps in cudaGridDependencySynchronize().
__global__ void __launch_bounds__(1024)
rcumsum_kernel(float* __restrict__ data)
{
    const int b    = blockIdx.x;
    const int t    = threadIdx.x;
    const int lane = t & 31;
    const int wid  = t >> 5;
    float4* p = reinterpret_cast<float4*>(data + (size_t)b * L) + t;

    // Wait for the dot kernel's stores (PDL trigger-based visibility).
    cudaGridDependencySynchronize();

    float4 x = *p;
    float v0 = x.x, v1 = x.y, v2 = x.z, v3 = x.w;
    float total = v0 + v1 + v2 + v3;

    // inclusive SUFFIX scan within warp: lane i -> sum over lanes >= i
    float s = total;
    #pragma unroll
    for (int off = 1; off < 32; off <<= 1) {
        float n = __shfl_down_sync(0xFFFFFFFFu, s, off);
        if (lane < 32 - off) s += n;
    }

    __shared__ float warp_off[32];
    {
        __shared__ float warp_tot[32];
        if (lane == 0) warp_tot[wid] = s;   // lane 0's s == warp full sum
        __syncthreads();

        if (wid == 0) {
            float ws = warp_tot[lane];
            float ss = ws;
            #pragma unroll
            for (int off = 1; off < 32; off <<= 1) {
                float n = __shfl_down_sync(0xFFFFFFFFu, ss, off);
                if (lane < 32 - off) ss += n;
            }
            warp_off[lane] = ss - ws;       // exclusive suffix of warp sums
        }
        __syncthreads();
    }

    // exclusive suffix for this thread: warps after mine + lanes after me
    float offset = warp_off[wid] + (s - total);

    float q3 = offset + v3;
    float q2 = q3 + v2;
    float q1 = q2 + v1;
    float q0 = q1 + v0;

    *p = make_float4(q0, q1, q2, q3);
}

extern "C" void kernel_launch(void* const* d_in, const int* in_sizes, int n_in,
                              void* d_out, int out_size)
{
    const float4* states4 = (const float4*)d_in[0];
    const float4* w4      = (const float4*)d_in[1];
    const float*  bias    = (const float*)d_in[2];
    float* out = (float*)d_out;

    dot_kernel<<<ROWS / 8, 256>>>(states4, w4, bias, out);

    // PDL launch of the scan: ramp overlaps the primary's execution.
    cudaLaunchConfig_t cfg = {};
    cfg.gridDim  = dim3(B, 1, 1);
    cfg.blockDim = dim3(1024, 1, 1);
    cfg.dynamicSmemBytes = 0;
    cfg.stream = 0;
    cudaLaunchAttribute attr[1];
    attr[0].id = cudaLaunchAttributeProgrammaticStreamSerialization;
    attr[0].val.programmaticStreamSerializationAllowed = 1;
    cfg.attrs = attr;
    cfg.numAttrs = 1;
    cudaLaunchKernelEx(&cfg, rcumsum_kernel, out);
}